// round 1
// baseline (speedup 1.0000x reference)
#include <cuda_runtime.h>
#include <cstddef>

// 2-level 2D Haar DWT, fully fused.
// Input : x [32,3,512,512] f32  -> 96 channels of 512x512
// Output: concat(a2,h2,v2,d2 [96,128,128], h1,v1,d1 [96,256,256]) f32
//
// Per 2x2 block {p,q;r,s}: a=(p+q+r+s)/2, h=(p+q-r-s)/2, v=(p-q+r-s)/2, d=(p-q-r+s)/2
// (h = detail along rows / approx along cols, matching pywt cH; v = cV.)
// Each thread: 4x4 input tile -> 4x(h1,v1,d1) + 1x(a2,h2,v2,d2), all in registers.

#define NCH   96
#define WIN   512
#define W1    256
#define W2    128
#define S2    (NCH * W2 * W2)   // 1,572,864
#define S1    (NCH * W1 * W1)   // 6,291,456

__global__ void __launch_bounds__(256, 8)
haar2_fused_kernel(const float* __restrict__ x, float* __restrict__ out)
{
    int tid = blockIdx.x * blockDim.x + threadIdx.x;
    int J = tid & (W2 - 1);          // level-2 col, fastest -> coalesced
    int I = (tid >> 7) & (W2 - 1);   // level-2 row
    int c = tid >> 14;               // channel
    if (c >= NCH) return;

    const float* xc = x + (size_t)c * (WIN * WIN) + (size_t)(I * 4) * WIN + (J * 4);

    // 4 aligned float4 loads = the full 4x4 tile
    float4 r0 = *reinterpret_cast<const float4*>(xc + 0 * WIN);
    float4 r1 = *reinterpret_cast<const float4*>(xc + 1 * WIN);
    float4 r2 = *reinterpret_cast<const float4*>(xc + 2 * WIN);
    float4 r3 = *reinterpret_cast<const float4*>(xc + 3 * WIN);

    // Level-1 on the four 2x2 sub-blocks
    // quad (bi,bj): rows (2bi,2bi+1) of tile, cols (2bj,2bj+1)
    float a00, h00, v00, d00, a01, h01, v01, d01;
    float a10, h10, v10, d10, a11, h11, v11, d11;
    {
        float p = r0.x, q = r0.y, r = r1.x, s = r1.y;
        a00 = (p + q + r + s) * 0.5f; h00 = (p + q - r - s) * 0.5f;
        v00 = (p - q + r - s) * 0.5f; d00 = (p - q - r + s) * 0.5f;
    }
    {
        float p = r0.z, q = r0.w, r = r1.z, s = r1.w;
        a01 = (p + q + r + s) * 0.5f; h01 = (p + q - r - s) * 0.5f;
        v01 = (p - q + r - s) * 0.5f; d01 = (p - q - r + s) * 0.5f;
    }
    {
        float p = r2.x, q = r2.y, r = r3.x, s = r3.y;
        a10 = (p + q + r + s) * 0.5f; h10 = (p + q - r - s) * 0.5f;
        v10 = (p - q + r - s) * 0.5f; d10 = (p - q - r + s) * 0.5f;
    }
    {
        float p = r2.z, q = r2.w, r = r3.z, s = r3.w;
        a11 = (p + q + r + s) * 0.5f; h11 = (p + q - r - s) * 0.5f;
        v11 = (p - q + r - s) * 0.5f; d11 = (p - q - r + s) * 0.5f;
    }

    // Output plane pointers within d_out
    float* out_a2 = out;
    float* out_h2 = out + S2;
    float* out_v2 = out + 2 * (size_t)S2;
    float* out_d2 = out + 3 * (size_t)S2;
    float* out_h1 = out + 4 * (size_t)S2;
    float* out_v1 = out + 4 * (size_t)S2 + (size_t)S1;
    float* out_d1 = out + 4 * (size_t)S2 + 2 * (size_t)S1;

    // Level-1 detail planes: rows 2I,2I+1 cols 2J,2J+1 -> two float2 stores each
    size_t b1 = (size_t)c * (W1 * W1) + (size_t)(2 * I) * W1 + (2 * J);
    *reinterpret_cast<float2*>(out_h1 + b1)      = make_float2(h00, h01);
    *reinterpret_cast<float2*>(out_h1 + b1 + W1) = make_float2(h10, h11);
    *reinterpret_cast<float2*>(out_v1 + b1)      = make_float2(v00, v01);
    *reinterpret_cast<float2*>(out_v1 + b1 + W1) = make_float2(v10, v11);
    *reinterpret_cast<float2*>(out_d1 + b1)      = make_float2(d00, d01);
    *reinterpret_cast<float2*>(out_d1 + b1 + W1) = make_float2(d10, d11);

    // Level-2 from the in-register cA1 quad
    size_t b2 = (size_t)c * (W2 * W2) + (size_t)I * W2 + J;
    out_a2[b2] = (a00 + a01 + a10 + a11) * 0.5f;
    out_h2[b2] = (a00 + a01 - a10 - a11) * 0.5f;
    out_v2[b2] = (a00 - a01 + a10 - a11) * 0.5f;
    out_d2[b2] = (a00 - a01 - a10 + a11) * 0.5f;
}

extern "C" void kernel_launch(void* const* d_in, const int* in_sizes, int n_in,
                              void* d_out, int out_size)
{
    const float* x = (const float*)d_in[0];
    float* out = (float*)d_out;
    int total_threads = NCH * W2 * W2;      // 1,572,864
    int block = 256;
    int grid = total_threads / block;       // 6144
    haar2_fused_kernel<<<grid, block>>>(x, out);
}

// round 3
// speedup vs baseline: 1.0183x; 1.0183x over previous
#include <cuda_runtime.h>
#include <cstddef>

// 2-level 2D Haar DWT, fully fused, 2 tiles per thread for MLP=8.
// Input : x [32,3,512,512] f32  -> 96 channels of 512x512
// Output: concat(a2,h2,v2,d2 [96,128,128], h1,v1,d1 [96,256,256]) f32
//
// Per 2x2 block {p,q;r,s}: a=(p+q+r+s)/2, h=(p+q-r-s)/2, v=(p-q+r-s)/2, d=(p-q-r+s)/2
// Each thread handles level-2 outputs (I,J) and (I,J+64): two 4x4 input tiles
// 256 floats apart, so every LDG.128 / STG in a warp is fully coalesced.

#define NCH   96
#define WIN   512
#define W1    256
#define W2    128
#define S2    (NCH * W2 * W2)   // 1,572,864
#define S1    (NCH * W1 * W1)   // 6,291,456

__device__ __forceinline__ void haar_quad(float p, float q, float r, float s,
                                          float& a, float& h, float& v, float& d)
{
    a = (p + q + r + s) * 0.5f;
    h = (p + q - r - s) * 0.5f;
    v = (p - q + r - s) * 0.5f;
    d = (p - q - r + s) * 0.5f;
}

__global__ void __launch_bounds__(256, 4)
haar2_fused2_kernel(const float* __restrict__ x, float* __restrict__ out)
{
    int tid = blockIdx.x * blockDim.x + threadIdx.x;
    int J = tid & 63;                // level-2 col (thread also does J+64)
    int I = (tid >> 6) & (W2 - 1);   // level-2 row
    int c = tid >> 13;               // channel (exact: grid covers 96*128*64)

    const float* xc = x + (size_t)c * (WIN * WIN) + (size_t)(I * 4) * WIN + (J * 4);

    // 8 front-batched float4 loads, streaming (read-once data)
    float4 a0 = __ldcs(reinterpret_cast<const float4*>(xc + 0 * WIN));
    float4 a1 = __ldcs(reinterpret_cast<const float4*>(xc + 1 * WIN));
    float4 a2r = __ldcs(reinterpret_cast<const float4*>(xc + 2 * WIN));
    float4 a3 = __ldcs(reinterpret_cast<const float4*>(xc + 3 * WIN));
    float4 b0 = __ldcs(reinterpret_cast<const float4*>(xc + 256 + 0 * WIN));
    float4 b1 = __ldcs(reinterpret_cast<const float4*>(xc + 256 + 1 * WIN));
    float4 b2r = __ldcs(reinterpret_cast<const float4*>(xc + 256 + 2 * WIN));
    float4 b3 = __ldcs(reinterpret_cast<const float4*>(xc + 256 + 3 * WIN));

    // ---- tile A (columns 4J..4J+3) ----
    float Aa00,Ah00,Av00,Ad00, Aa01,Ah01,Av01,Ad01;
    float Aa10,Ah10,Av10,Ad10, Aa11,Ah11,Av11,Ad11;
    haar_quad(a0.x, a0.y, a1.x, a1.y, Aa00, Ah00, Av00, Ad00);
    haar_quad(a0.z, a0.w, a1.z, a1.w, Aa01, Ah01, Av01, Ad01);
    haar_quad(a2r.x, a2r.y, a3.x, a3.y, Aa10, Ah10, Av10, Ad10);
    haar_quad(a2r.z, a2r.w, a3.z, a3.w, Aa11, Ah11, Av11, Ad11);

    // ---- tile B (columns 4J+256..4J+259) ----
    float Ba00,Bh00,Bv00,Bd00, Ba01,Bh01,Bv01,Bd01;
    float Ba10,Bh10,Bv10,Bd10, Ba11,Bh11,Bv11,Bd11;
    haar_quad(b0.x, b0.y, b1.x, b1.y, Ba00, Bh00, Bv00, Bd00);
    haar_quad(b0.z, b0.w, b1.z, b1.w, Ba01, Bh01, Bv01, Bd01);
    haar_quad(b2r.x, b2r.y, b3.x, b3.y, Ba10, Bh10, Bv10, Bd10);
    haar_quad(b2r.z, b2r.w, b3.z, b3.w, Ba11, Bh11, Bv11, Bd11);

    float* out_a2 = out;
    float* out_h2 = out + S2;
    float* out_v2 = out + 2 * (size_t)S2;
    float* out_d2 = out + 3 * (size_t)S2;
    float* out_h1 = out + 4 * (size_t)S2;
    float* out_v1 = out + 4 * (size_t)S2 + (size_t)S1;
    float* out_d1 = out + 4 * (size_t)S2 + 2 * (size_t)S1;

    // Level-1 detail planes: tile A at cols 2J, tile B at cols 2J+128
    size_t p1 = (size_t)c * (W1 * W1) + (size_t)(2 * I) * W1 + (2 * J);
    __stcs(reinterpret_cast<float2*>(out_h1 + p1),            make_float2(Ah00, Ah01));
    __stcs(reinterpret_cast<float2*>(out_h1 + p1 + W1),       make_float2(Ah10, Ah11));
    __stcs(reinterpret_cast<float2*>(out_h1 + p1 + 128),      make_float2(Bh00, Bh01));
    __stcs(reinterpret_cast<float2*>(out_h1 + p1 + 128 + W1), make_float2(Bh10, Bh11));
    __stcs(reinterpret_cast<float2*>(out_v1 + p1),            make_float2(Av00, Av01));
    __stcs(reinterpret_cast<float2*>(out_v1 + p1 + W1),       make_float2(Av10, Av11));
    __stcs(reinterpret_cast<float2*>(out_v1 + p1 + 128),      make_float2(Bv00, Bv01));
    __stcs(reinterpret_cast<float2*>(out_v1 + p1 + 128 + W1), make_float2(Bv10, Bv11));
    __stcs(reinterpret_cast<float2*>(out_d1 + p1),            make_float2(Ad00, Ad01));
    __stcs(reinterpret_cast<float2*>(out_d1 + p1 + W1),       make_float2(Ad10, Ad11));
    __stcs(reinterpret_cast<float2*>(out_d1 + p1 + 128),      make_float2(Bd00, Bd01));
    __stcs(reinterpret_cast<float2*>(out_d1 + p1 + 128 + W1), make_float2(Bd10, Bd11));

    // Level-2: elements (I,J) and (I,J+64) of each plane
    size_t p2 = (size_t)c * (W2 * W2) + (size_t)I * W2 + J;
    __stcs(out_a2 + p2,      (Aa00 + Aa01 + Aa10 + Aa11) * 0.5f);
    __stcs(out_a2 + p2 + 64, (Ba00 + Ba01 + Ba10 + Ba11) * 0.5f);
    __stcs(out_h2 + p2,      (Aa00 + Aa01 - Aa10 - Aa11) * 0.5f);
    __stcs(out_h2 + p2 + 64, (Ba00 + Ba01 - Ba10 - Ba11) * 0.5f);
    __stcs(out_v2 + p2,      (Aa00 - Aa01 + Aa10 - Aa11) * 0.5f);
    __stcs(out_v2 + p2 + 64, (Ba00 - Ba01 + Ba10 - Ba11) * 0.5f);
    __stcs(out_d2 + p2,      (Aa00 - Aa01 - Aa10 + Aa11) * 0.5f);
    __stcs(out_d2 + p2 + 64, (Ba00 - Ba01 - Ba10 + Ba11) * 0.5f);
}

extern "C" void kernel_launch(void* const* d_in, const int* in_sizes, int n_in,
                              void* d_out, int out_size)
{
    const float* x = (const float*)d_in[0];
    float* out = (float*)d_out;
    int total_threads = NCH * W2 * 64;   // 786,432
    int block = 256;
    int grid = total_threads / block;    // 3072
    haar2_fused2_kernel<<<grid, block>>>(x, out);
}